// round 1
// baseline (speedup 1.0000x reference)
#include <cuda_runtime.h>

// Problem constants
#define Nn   10000
#define Bb   4
#define Ff   16
#define Tt   12
#define Ee   160000
#define Cc   64
#define ROW  768          // Bb*Tt*Ff floats per node
#define ROW4 192          // ROW/4 (float4)

// ---------------- scratch (device globals; no allocation) ----------------
__device__ float g_Tx0[Nn * ROW];
__device__ float g_Tx1[Nn * ROW];
__device__ float g_Tx2[Nn * ROW];
__device__ float g_deg[Nn];
__device__ int   g_degin[Nn];
__device__ int   g_off[Nn + 1];
__device__ int   g_cur[Nn];
__device__ int   g_srcs[Ee];

// ---------------- graph preprocessing ----------------
__global__ void k_zero() {
    int i = blockIdx.x * blockDim.x + threadIdx.x;
    if (i < Nn) { g_deg[i] = 0.0f; g_degin[i] = 0; }
}

__global__ void k_count(const int* __restrict__ ei) {
    int e = blockIdx.x * blockDim.x + threadIdx.x;
    if (e < Ee) {
        atomicAdd(&g_deg[ei[e]], 1.0f);       // out-degree by row
        atomicAdd(&g_degin[ei[Ee + e]], 1);   // in-degree by col
    }
}

// single-block exclusive scan over g_degin -> g_off, g_cur
__global__ void k_scan() {
    __shared__ int part[1024];
    int t = threadIdx.x;
    const int CH = 10;                 // 1024*10 >= Nn
    int base = t * CH;
    int local[CH];
    int s = 0;
#pragma unroll
    for (int i = 0; i < CH; i++) {
        int idx = base + i;
        int v = (idx < Nn) ? g_degin[idx] : 0;
        local[i] = v; s += v;
    }
    part[t] = s;
    __syncthreads();
    for (int off = 1; off < 1024; off <<= 1) {
        int v = (t >= off) ? part[t - off] : 0;
        __syncthreads();
        part[t] += v;
        __syncthreads();
    }
    int pre = (t == 0) ? 0 : part[t - 1];
#pragma unroll
    for (int i = 0; i < CH; i++) {
        int idx = base + i;
        if (idx < Nn) { g_off[idx] = pre; g_cur[idx] = pre; pre += local[i]; }
    }
    if (t == 1023) g_off[Nn] = part[1023];
}

__global__ void k_fill(const int* __restrict__ ei) {
    int e = blockIdx.x * blockDim.x + threadIdx.x;
    if (e < Ee) {
        int c = ei[Ee + e];
        int p = atomicAdd(&g_cur[c], 1);
        g_srcs[p] = ei[e];
    }
}

// ---------------- transpose x (B,N,F,T) -> Tx0 (N,B,T,F) ----------------
__global__ void k_transpose(const float* __restrict__ x) {
    int bn = blockIdx.x;               // b*Nn + n
    int b = bn / Nn, n = bn - b * Nn;
    __shared__ float tile[ROW4];
    int tid = threadIdx.x;             // 0..191
    tile[tid] = x[bn * ROW4 + tid];    // (f*12 + t)
    __syncthreads();
    int t = tid >> 4, f = tid & 15;
    g_Tx0[n * ROW + b * ROW4 + tid] = tile[f * Tt + t];  // (t*16 + f)
}

// ---------------- Lhat via CSR gather ----------------
// Tx1 = (2/lam)*(deg*Tx0 - agg(Tx0)) - Tx0
__global__ void k_lhat1(const float* __restrict__ lamp) {
    int n = blockIdx.x, j = threadIdx.x;     // j: float4 index 0..191
    const float4* u = (const float4*)g_Tx0;
    float4 acc = make_float4(0.f, 0.f, 0.f, 0.f);
    int e = g_off[n], e1 = g_off[n + 1];
    for (; e + 4 <= e1; e += 4) {
        int s0 = g_srcs[e], s1 = g_srcs[e + 1], s2 = g_srcs[e + 2], s3 = g_srcs[e + 3];
        float4 v0 = u[s0 * ROW4 + j], v1 = u[s1 * ROW4 + j];
        float4 v2 = u[s2 * ROW4 + j], v3 = u[s3 * ROW4 + j];
        acc.x += (v0.x + v1.x) + (v2.x + v3.x);
        acc.y += (v0.y + v1.y) + (v2.y + v3.y);
        acc.z += (v0.z + v1.z) + (v2.z + v3.z);
        acc.w += (v0.w + v1.w) + (v2.w + v3.w);
    }
    for (; e < e1; e++) {
        float4 v = u[g_srcs[e] * ROW4 + j];
        acc.x += v.x; acc.y += v.y; acc.z += v.z; acc.w += v.w;
    }
    float4 un = u[n * ROW4 + j];
    float c2 = 2.0f / lamp[0];
    float dn = g_deg[n];
    float4 r;
    r.x = c2 * (dn * un.x - acc.x) - un.x;
    r.y = c2 * (dn * un.y - acc.y) - un.y;
    r.z = c2 * (dn * un.z - acc.z) - un.z;
    r.w = c2 * (dn * un.w - acc.w) - un.w;
    ((float4*)g_Tx1)[n * ROW4 + j] = r;
}

// Tx2 = 2*Lhat(Tx1) - Tx0
__global__ void k_lhat2(const float* __restrict__ lamp) {
    int n = blockIdx.x, j = threadIdx.x;
    const float4* u = (const float4*)g_Tx1;
    float4 acc = make_float4(0.f, 0.f, 0.f, 0.f);
    int e = g_off[n], e1 = g_off[n + 1];
    for (; e + 4 <= e1; e += 4) {
        int s0 = g_srcs[e], s1 = g_srcs[e + 1], s2 = g_srcs[e + 2], s3 = g_srcs[e + 3];
        float4 v0 = u[s0 * ROW4 + j], v1 = u[s1 * ROW4 + j];
        float4 v2 = u[s2 * ROW4 + j], v3 = u[s3 * ROW4 + j];
        acc.x += (v0.x + v1.x) + (v2.x + v3.x);
        acc.y += (v0.y + v1.y) + (v2.y + v3.y);
        acc.z += (v0.z + v1.z) + (v2.z + v3.z);
        acc.w += (v0.w + v1.w) + (v2.w + v3.w);
    }
    for (; e < e1; e++) {
        float4 v = u[g_srcs[e] * ROW4 + j];
        acc.x += v.x; acc.y += v.y; acc.z += v.z; acc.w += v.w;
    }
    float4 un = u[n * ROW4 + j];
    float4 t0 = ((const float4*)g_Tx0)[n * ROW4 + j];
    float c2 = 2.0f / lamp[0];
    float dn = g_deg[n];
    float4 r;
    r.x = 2.0f * (c2 * (dn * un.x - acc.x) - un.x) - t0.x;
    r.y = 2.0f * (c2 * (dn * un.y - acc.y) - un.y) - t0.y;
    r.z = 2.0f * (c2 * (dn * un.z - acc.z) - un.z) - t0.z;
    r.w = 2.0f * (c2 * (dn * un.w - acc.w) - un.w) - t0.w;
    ((float4*)g_Tx2)[n * ROW4 + j] = r;
}

// ---------------- fused cheb-proj + temporal conv + residual + LN ----------------
// block = 256 threads = 4 groups of 64; group g handles (n = q, b = g)
// smem layout (floats):
//   wch  [0,3072)     cheb weights (k*16+f)*64+c  (same linear order as input)
//   wt   [3072,15360) time weights [d][ci][co]
//   wr   [15360,16384) res weights [f][co]
//   cb/trb/gma/bta [16384,16640)
//   txT  [16640,18944)  per group 576: (j)*12+t
//   spad [18944,23040)  per group 1024: (ci)*16 + (t+1), zero-padded boundaries
//   xrs  [23040,23808)  per group 192: f*12+t
//   hs   [23808,26880)  per group 768: t*64+c
//   mus  [26880,26928)  rss [26928,26976)
#define SMEM_FLOATS 26976

__global__ void __launch_bounds__(256, 2)
k_fused(const float* __restrict__ x,
        const float* __restrict__ chebW, const float* __restrict__ chebB,
        const float* __restrict__ timeW, const float* __restrict__ timeB,
        const float* __restrict__ resW,  const float* __restrict__ resB,
        const float* __restrict__ gamma, const float* __restrict__ beta,
        float* __restrict__ out)
{
    extern __shared__ float sm[];
    float* wch = sm;
    float* wt  = sm + 3072;
    float* wr  = sm + 15360;
    float* cb  = sm + 16384;
    float* trb = sm + 16448;
    float* gma = sm + 16512;
    float* bta = sm + 16576;
    float* txT = sm + 16640;
    float* spad = sm + 18944;
    float* xrs = sm + 23040;
    float* hs  = sm + 23808;
    float* mus = sm + 26880;
    float* rss = sm + 26928;

    int tid = threadIdx.x;

    // --- one-time weight staging ---
    for (int i = tid; i < 3072; i += 256) wch[i] = chebW[i];
    for (int i = tid; i < 12288; i += 256) {
        int d = i / 4096; int r = i - d * 4096;
        int ci = r >> 6; int co = r & 63;
        wt[i] = timeW[co * 192 + ci * 3 + d];
    }
    for (int i = tid; i < 1024; i += 256) {
        int f = i >> 6; int co = i & 63;
        wr[i] = resW[co * 16 + f];
    }
    if (tid < 64) {
        cb[tid]  = chebB[tid];
        trb[tid] = timeB[tid] + resB[tid];
        gma[tid] = gamma[tid];
        bta[tid] = beta[tid];
    }
    // zero spad boundary columns once (only [1..12] ever rewritten)
    {
        int g = tid >> 6; int ci = tid & 63;
        float* sp = spad + g * 1024 + ci * 16;
        sp[0] = 0.f; sp[13] = 0.f; sp[14] = 0.f; sp[15] = 0.f;
    }
    __syncthreads();

    const int g = tid >> 6;        // group = batch b
    const int c = tid & 63;        // channel
    const int lane = tid & 31;
    const int w01 = (tid >> 5) & 1;

    float* mytxT = txT + g * 576;
    float* myspad = spad + g * 1024;
    float* myxr = xrs + g * 192;
    float* myhs = hs + g * 768;
    float* mymu = mus + g * 12;
    float* myrs = rss + g * 12;

    for (int q = blockIdx.x; q < Nn; q += gridDim.x) {
        const int n = q;

        // ---- Stage 0: cooperative loads ----
        for (int i = tid; i < 2304; i += 256) {
            int gg = i / 576; int r = i - gg * 576;
            int k = r / 192; int rr = r - k * 192;   // rr = t*16+f
            int t = rr >> 4, f = rr & 15;
            const float* src = (k == 0) ? g_Tx0 : (k == 1) ? g_Tx1 : g_Tx2;
            float v = src[n * ROW + gg * ROW4 + rr];
            txT[gg * 576 + (k * 16 + f) * 12 + t] = v;
        }
        for (int i = tid; i < 768; i += 256) {
            int gg = i / 192; int r = i - gg * 192;
            xrs[gg * 192 + r] = x[(gg * Nn + n) * ROW4 + r];
        }
        __syncthreads();

        // ---- Stage A: cheb projection, relu -> spad ----
        {
            float acc[12];
            float bias = cb[c];
#pragma unroll
            for (int t = 0; t < 12; t++) acc[t] = bias;
#pragma unroll
            for (int j = 0; j < 48; j++) {
                float w = wch[j * 64 + c];
                const float4* tp = (const float4*)(mytxT + j * 12);
                float4 a0 = tp[0], a1 = tp[1], a2 = tp[2];
                acc[0] += a0.x * w; acc[1] += a0.y * w; acc[2]  += a0.z * w; acc[3]  += a0.w * w;
                acc[4] += a1.x * w; acc[5] += a1.y * w; acc[6]  += a1.z * w; acc[7]  += a1.w * w;
                acc[8] += a2.x * w; acc[9] += a2.y * w; acc[10] += a2.z * w; acc[11] += a2.w * w;
            }
            float* sp = myspad + c * 16;
#pragma unroll
            for (int t = 0; t < 12; t++) sp[t + 1] = fmaxf(acc[t], 0.f);
        }
        __syncthreads();

        // ---- Stage B: temporal conv + residual, relu ----
        float h[12];
        {
            float bb = trb[c];
#pragma unroll
            for (int t = 0; t < 12; t++) h[t] = bb;
            for (int ci = 0; ci < 64; ci++) {
                const float4* sp4 = (const float4*)(myspad + ci * 16);
                float4 s0 = sp4[0], s1 = sp4[1], s2 = sp4[2], s3 = sp4[3];
                float sv[16] = { s0.x, s0.y, s0.z, s0.w,  s1.x, s1.y, s1.z, s1.w,
                                 s2.x, s2.y, s2.z, s2.w,  s3.x, s3.y, s3.z, s3.w };
                float w0 = wt[ci * 64 + c];
                float w1 = wt[4096 + ci * 64 + c];
                float w2 = wt[8192 + ci * 64 + c];
#pragma unroll
                for (int t = 0; t < 12; t++)
                    h[t] += sv[t] * w0 + sv[t + 1] * w1 + sv[t + 2] * w2;
            }
#pragma unroll
            for (int f = 0; f < 16; f++) {
                float w = wr[f * 64 + c];
                const float4* xp = (const float4*)(myxr + f * 12);
                float4 x0 = xp[0], x1 = xp[1], x2 = xp[2];
                float xv[12] = { x0.x, x0.y, x0.z, x0.w,  x1.x, x1.y, x1.z, x1.w,
                                 x2.x, x2.y, x2.z, x2.w };
#pragma unroll
                for (int t = 0; t < 12; t++) h[t] += xv[t] * w;
            }
#pragma unroll
            for (int t = 0; t < 12; t++) {
                h[t] = fmaxf(h[t], 0.f);
                myhs[t * 64 + c] = h[t];
            }
        }
        __syncthreads();

        // ---- LN stats: each of the group's 2 warps reduces 6 t-rows ----
        {
#pragma unroll
            for (int r = 0; r < 6; r++) {
                int t = w01 * 6 + r;
                float v1 = myhs[t * 64 + lane];
                float v2 = myhs[t * 64 + 32 + lane];
                float s = v1 + v2;
                float sq = v1 * v1 + v2 * v2;
#pragma unroll
                for (int o = 16; o > 0; o >>= 1) {
                    s  += __shfl_xor_sync(0xffffffffu, s, o);
                    sq += __shfl_xor_sync(0xffffffffu, sq, o);
                }
                if (lane == 0) {
                    float mu = s * (1.0f / 64.0f);
                    float var = sq * (1.0f / 64.0f) - mu * mu;
                    mymu[t] = mu;
                    myrs[t] = rsqrtf(var + 1e-5f);
                }
            }
        }
        __syncthreads();

        // ---- normalize + write out (B,N,C,T), coalesced float4 ----
        {
            float ga = gma[c], be = bta[c];
            float o[12];
#pragma unroll
            for (int t = 0; t < 12; t++)
                o[t] = (h[t] - mymu[t]) * myrs[t] * ga + be;
            float* op = out + (((size_t)g * Nn + n) * 64 + c) * 12;
            float4* op4 = (float4*)op;
            op4[0] = make_float4(o[0], o[1], o[2],  o[3]);
            op4[1] = make_float4(o[4], o[5], o[6],  o[7]);
            op4[2] = make_float4(o[8], o[9], o[10], o[11]);
        }
        __syncthreads();
    }
}

// ---------------- launcher ----------------
extern "C" void kernel_launch(void* const* d_in, const int* in_sizes, int n_in,
                              void* d_out, int out_size)
{
    const float* x     = (const float*)d_in[0];
    const int*   ei    = (const int*)d_in[1];
    const float* lam   = (const float*)d_in[2];
    const float* chebW = (const float*)d_in[3];
    const float* chebB = (const float*)d_in[4];
    const float* timeW = (const float*)d_in[5];
    const float* timeB = (const float*)d_in[6];
    const float* resW  = (const float*)d_in[7];
    const float* resB  = (const float*)d_in[8];
    const float* gma   = (const float*)d_in[9];
    const float* bta   = (const float*)d_in[10];
    float* out = (float*)d_out;

    k_zero<<<(Nn + 255) / 256, 256>>>();
    k_count<<<(Ee + 255) / 256, 256>>>(ei);
    k_scan<<<1, 1024>>>();
    k_fill<<<(Ee + 255) / 256, 256>>>(ei);
    k_transpose<<<Bb * Nn, 192>>>(x);
    k_lhat1<<<Nn, 192>>>(lam);
    k_lhat2<<<Nn, 192>>>(lam);

    cudaFuncSetAttribute(k_fused, cudaFuncAttributeMaxDynamicSharedMemorySize,
                         SMEM_FLOATS * 4);
    k_fused<<<1480, 256, SMEM_FLOATS * 4>>>(x, chebW, chebB, timeW, timeB,
                                            resW, resB, gma, bta, out);
}